// round 3
// baseline (speedup 1.0000x reference)
#include <cuda_runtime.h>
#include <math.h>

#define Bn 64
#define Nn 128
#define Dn 32
#define Gn 127              // N-1
#define Pn (Nn*(Nn-1))      // 16256
#define H1n 32
#define H2n 32
#define HFn 16
#define EPSf 1e-5f

// ---------------- scratch (static device globals; no allocation) -------------
__device__ float g_U[Bn*Nn*Dn];      // U'[b][n][c] = x@W1_top + b1
__device__ float g_V[Bn*Nn*Dn];      // V [b][n][c] = x@W1_bot
__device__ float g_sumU[Nn], g_sumU2[Nn], g_sumV[Nn], g_sumV2[Nn];
__device__ float g_C[Nn*Nn];         // C[s][t] = sum_{b,c} U'[b,s,c]*V[b,t,c]
__device__ float g_scale[Pn], g_shift[Pn];
__device__ float g_f[Bn*Nn*HFn];     // pre-LN features of final MLP
__device__ float g_lnp[2*HFn];       // [0:16) scale, [16:32) shift

__device__ __forceinline__ float leaky(float x) { return x > 0.f ? x : 0.01f * x; }

// ---------------- Kernel A: per-node projections + per-node stats ------------
// grid = N, block = 64 (one thread per batch element)
__global__ void kA(const float* __restrict__ inp, const float* __restrict__ W1,
                   const float* __restrict__ b1) {
    const int n = blockIdx.x;
    const int b = threadIdx.x;     // 0..63
    __shared__ float W1s[64*32];
    __shared__ float red[64*4];
    for (int idx = b; idx < 64*32; idx += 64) W1s[idx] = W1[idx];
    __syncthreads();

    float x[32];
    const float4* xp = (const float4*)(inp + ((size_t)b*Nn + n)*Dn);
    #pragma unroll
    for (int q = 0; q < 8; q++) {
        float4 v = xp[q];
        x[4*q+0]=v.x; x[4*q+1]=v.y; x[4*q+2]=v.z; x[4*q+3]=v.w;
    }
    float su=0.f, su2=0.f, sv=0.f, sv2=0.f;
    float* Uo = g_U + ((size_t)b*Nn + n)*Dn;
    float* Vo = g_V + ((size_t)b*Nn + n)*Dn;
    #pragma unroll 4
    for (int c = 0; c < 32; c++) {
        float u = b1[c];
        float v = 0.f;
        #pragma unroll
        for (int k = 0; k < 32; k++) {
            u += x[k] * W1s[k*32 + c];
            v += x[k] * W1s[(32+k)*32 + c];
        }
        Uo[c] = u; Vo[c] = v;
        su += u; su2 += u*u; sv += v; sv2 += v*v;
    }
    red[b] = su; red[64+b] = su2; red[128+b] = sv; red[192+b] = sv2;
    __syncthreads();
    for (int s = 32; s > 0; s >>= 1) {
        if (b < s) {
            red[b]     += red[b+s];
            red[64+b]  += red[64+b+s];
            red[128+b] += red[128+b+s];
            red[192+b] += red[192+b+s];
        }
        __syncthreads();
    }
    if (b == 0) {
        g_sumU[n]  = red[0];
        g_sumU2[n] = red[64];
        g_sumV[n]  = red[128];
        g_sumV2[n] = red[192];
    }
}

// ---------------- Kernel B: cross term C[s,t], 128x128, K = 64*32 ------------
// grid = (8,8), block = 256 (16x16 tile)
__global__ void kB() {
    const int t0 = blockIdx.x * 16;
    const int s0 = blockIdx.y * 16;
    const int tx = threadIdx.x & 15;
    const int ty = threadIdx.x >> 4;
    __shared__ float Us[16][33];
    __shared__ float Vs[16][33];
    float acc = 0.f;
    for (int b = 0; b < Bn; b++) {
        __syncthreads();
        {
            int idx = threadIdx.x;           // 0..255 -> 2 loads each (512 elems)
            int r = idx >> 5, c = idx & 31;
            Us[r][c] = g_U[((size_t)b*Nn + s0 + r)*Dn + c];
            Vs[r][c] = g_V[((size_t)b*Nn + t0 + r)*Dn + c];
            idx += 256; r = idx >> 5; c = idx & 31;
            Us[r][c] = g_U[((size_t)b*Nn + s0 + r)*Dn + c];
            Vs[r][c] = g_V[((size_t)b*Nn + t0 + r)*Dn + c];
        }
        __syncthreads();
        #pragma unroll
        for (int c = 0; c < 32; c++) acc += Us[ty][c] * Vs[tx][c];
    }
    g_C[(s0+ty)*Nn + (t0+tx)] = acc;
}

// ---------------- Kernel B2: per-pair LN scale/shift --------------------------
__global__ void kB2(const float* __restrict__ g1, const float* __restrict__ be1) {
    int p = blockIdx.x * 256 + threadIdx.x;
    if (p >= Pn) return;
    int i = p / Gn;
    int e = p - i * Gn;
    int t = e + (e >= i);
    const float inv = 1.0f / 2048.0f;   // 1/(B*H1)
    float m  = (g_sumU[i] + g_sumV[t]) * inv;
    float e2 = (g_sumU2[i] + g_sumV2[t] + 2.0f * g_C[i*Nn + t]) * inv;
    float var = e2 - m * m;
    float r = rsqrtf(var + EPSf);
    float sc = r * g1[p];
    g_scale[p] = sc;
    g_shift[p] = be1[p] - m * sc;
}

// ---------------- Kernel C: fused per-edge MLP + aggregate + f ---------------
// grid = (N, B), block = 128. Thread e handles edge p = i*127+e.
__global__ void __launch_bounds__(128) kC(
        const float* __restrict__ inp,
        const float* __restrict__ W2, const float* __restrict__ b2,
        const float* __restrict__ W3, const float* __restrict__ b3,
        const float* __restrict__ Wf1, const float* __restrict__ bf1,
        float* __restrict__ outEdges) {
    const int i = blockIdx.x;
    const int b = blockIdx.y;
    const int e = threadIdx.x;

    __shared__ float W2t[32*32];   // W2t[c*32+k] = W2[k*32+c]  (rows 128B, float4-able)
    __shared__ float W3t[33*32];   // W3t[c*32+k] = W3[k*33+c]
    __shared__ float b2s[32], b3s[33], us[32], xs[32];
    __shared__ float red[127*33];  // per-edge weighted messages
    __shared__ float red2[4*32];   // stage-1 partial sums

    for (int idx = e; idx < 1024; idx += 128) {
        int c = idx >> 5, k = idx & 31;
        W2t[idx] = W2[k*32 + c];
    }
    for (int idx = e; idx < 1056; idx += 128) {
        int c = idx >> 5, k = idx & 31;
        W3t[idx] = W3[k*33 + c];
    }
    if (e < 32) {
        b2s[e] = b2[e];
        us[e]  = g_U[((size_t)b*Nn + i)*Dn + e];
        xs[e]  = inp[((size_t)b*Nn + i)*Dn + e];
    }
    if (e < 33) b3s[e] = b3[e];
    __syncthreads();

    if (e < Gn) {
        const int t = e + (e >= i);
        const int p = i * Gn + e;
        const float sc = g_scale[p];
        const float sh = g_shift[p];
        const float4* vr = (const float4*)(g_V + ((size_t)b*Nn + t)*Dn);

        float a[32];
        #pragma unroll
        for (int q = 0; q < 8; q++) {
            float4 v = vr[q];
            float h0 = (us[4*q+0] + v.x) * sc + sh;
            float h1 = (us[4*q+1] + v.y) * sc + sh;
            float h2 = (us[4*q+2] + v.z) * sc + sh;
            float h3 = (us[4*q+3] + v.w) * sc + sh;
            a[4*q+0] = leaky(h0); a[4*q+1] = leaky(h1);
            a[4*q+2] = leaky(h2); a[4*q+3] = leaky(h3);
        }

        // MLP layer 2: vectorized shared weight reads (1 LDS.128 : 4 FFMA)
        float a2[32];
        #pragma unroll 4
        for (int c = 0; c < 32; c++) {
            float acc = b2s[c];
            const float4* wr = (const float4*)(W2t + c*32);
            #pragma unroll
            for (int j = 0; j < 8; j++) {
                float4 w = wr[j];
                acc += a[4*j+0] * w.x;
                acc += a[4*j+1] * w.y;
                acc += a[4*j+2] * w.z;
                acc += a[4*j+3] * w.w;
            }
            a2[c] = leaky(acc);
        }

        // MLP layer 3 channel 0 -> edge gate
        float acc0 = b3s[0];
        {
            const float4* wr = (const float4*)(W3t);
            #pragma unroll
            for (int j = 0; j < 8; j++) {
                float4 w = wr[j];
                acc0 += a2[4*j+0] * w.x;
                acc0 += a2[4*j+1] * w.y;
                acc0 += a2[4*j+2] * w.z;
                acc0 += a2[4*j+3] * w.w;
            }
        }
        float edge = 1.0f / (1.0f + __expf(-acc0));
        outEdges[(size_t)b * Pn + p] = edge;

        // MLP layer 3 channels 1..32 -> weighted messages
        #pragma unroll 4
        for (int c = 1; c < 33; c++) {
            float acc = b3s[c];
            const float4* wr = (const float4*)(W3t + c*32);
            #pragma unroll
            for (int j = 0; j < 8; j++) {
                float4 w = wr[j];
                acc += a2[4*j+0] * w.x;
                acc += a2[4*j+1] * w.y;
                acc += a2[4*j+2] * w.z;
                acc += a2[4*j+3] * w.w;
            }
            red[e*33 + (c-1)] = edge * acc;
        }
    }
    __syncthreads();

    // stage 1: 128 threads, quarter q sums 32 (or 31) rows for channel c
    {
        const int q = e >> 5;        // 0..3
        const int c = e & 31;
        const int r0 = q * 32;
        const int r1 = (q == 3) ? 127 : r0 + 32;
        float s = 0.f;
        for (int r = r0; r < r1; r++) s += red[r*33 + c];
        red2[q*32 + c] = s;
    }
    __syncthreads();

    if (e < HFn) {
        float acc = bf1[e];
        #pragma unroll
        for (int k = 0; k < 32; k++) acc += xs[k] * Wf1[k*HFn + e];
        #pragma unroll
        for (int k = 0; k < 32; k++) {
            float aggk = red2[k] + red2[32+k] + red2[64+k] + red2[96+k];
            acc += aggk * Wf1[(32+k)*HFn + e];
        }
        g_f[((size_t)b*Nn + i)*HFn + e] = acc;
    }
}

// ---------------- Kernel E: column stats of f -> LN params -------------------
// single block, 512 threads; thread j = tid&15, group = tid>>4 (32 groups)
__global__ void kE(const float* __restrict__ gf, const float* __restrict__ bef) {
    const int tid = threadIdx.x;
    __shared__ float rs[512], rs2[512];
    const int j = tid & 15;
    float s = 0.f, s2 = 0.f;
    for (int r = (tid >> 4); r < Bn*Nn; r += 32) {
        float v = g_f[r*HFn + j];
        s += v; s2 += v * v;
    }
    rs[tid] = s; rs2[tid] = s2;
    __syncthreads();
    for (int st = 256; st >= 16; st >>= 1) {
        if (tid < st) { rs[tid] += rs[tid+st]; rs2[tid] += rs2[tid+st]; }
        __syncthreads();
    }
    if (tid < HFn) {
        const float invR = 1.0f / (float)(Bn*Nn);
        float mean = rs[tid] * invR;
        float var  = rs2[tid] * invR - mean * mean;
        float r = rsqrtf(var + EPSf);
        float sc = r * gf[tid];
        g_lnp[tid]       = sc;
        g_lnp[16 + tid]  = bef[tid] - mean * sc;
    }
}

// ---------------- Kernel F: final MLP -> out ---------------------------------
// grid = 32, block = 256; one row per thread
__global__ void kF(const float* __restrict__ Wf2, const float* __restrict__ bf2,
                   float* __restrict__ outp) {
    __shared__ float Wf2s[16*32];
    __shared__ float lnsc[16], lnsh[16], bf2s[32];
    const int tid = threadIdx.x;
    for (int idx = tid; idx < 16*32; idx += 256) Wf2s[idx] = Wf2[idx];
    if (tid < 16) { lnsc[tid] = g_lnp[tid]; lnsh[tid] = g_lnp[16+tid]; }
    if (tid < 32) bf2s[tid] = bf2[tid];
    __syncthreads();

    const int r = blockIdx.x * 256 + tid;   // 0..8191
    float gq[16];
    #pragma unroll
    for (int j = 0; j < 16; j++) {
        float v = g_f[r*HFn + j];
        gq[j] = leaky(v * lnsc[j] + lnsh[j]);
    }
    float4* op = (float4*)(outp + (size_t)r * Dn);
    #pragma unroll
    for (int q = 0; q < 8; q++) {
        float o[4];
        #pragma unroll
        for (int u = 0; u < 4; u++) {
            int c = 4*q + u;
            float acc = bf2s[c];
            #pragma unroll
            for (int j = 0; j < 16; j++) acc += gq[j] * Wf2s[j*32 + c];
            o[u] = acc;
        }
        op[q] = make_float4(o[0], o[1], o[2], o[3]);
    }
}

// ---------------- launch ------------------------------------------------------
extern "C" void kernel_launch(void* const* d_in, const int* in_sizes, int n_in,
                              void* d_out, int out_size) {
    const float* inp = (const float*)d_in[0];
    // d_in[1]=src, d_in[2]=tgt (structure known analytically, unused)
    const float* W1  = (const float*)d_in[3];
    const float* b1  = (const float*)d_in[4];
    const float* g1  = (const float*)d_in[5];
    const float* be1 = (const float*)d_in[6];
    const float* W2  = (const float*)d_in[7];
    const float* b2  = (const float*)d_in[8];
    const float* W3  = (const float*)d_in[9];
    const float* b3  = (const float*)d_in[10];
    const float* Wf1 = (const float*)d_in[11];
    const float* bf1 = (const float*)d_in[12];
    const float* gf  = (const float*)d_in[13];
    const float* bef = (const float*)d_in[14];
    const float* Wf2 = (const float*)d_in[15];
    const float* bf2 = (const float*)d_in[16];

    float* outEdges = (float*)d_out;                       // (B, P)
    float* outFeat  = (float*)d_out + (size_t)Bn * Pn;     // (B, N, D)

    kA<<<Nn, 64>>>(inp, W1, b1);
    kB<<<dim3(8, 8), 256>>>();
    kB2<<<(Pn + 255) / 256, 256>>>(g1, be1);
    kC<<<dim3(Nn, Bn), 128>>>(inp, W2, b2, W3, b3, Wf1, bf1, outEdges);
    kE<<<1, 512>>>(gf, bef);
    kF<<<32, 256>>>(Wf2, bf2, outFeat);
}

// round 4
// speedup vs baseline: 1.3010x; 1.3010x over previous
#include <cuda_runtime.h>
#include <math.h>

#define Bn 64
#define Nn 128
#define Dn 32
#define Gn 127              // N-1
#define Pn (Nn*(Nn-1))      // 16256
#define HFn 16
#define EPSf 1e-5f

// ---------------- scratch (static device globals; no allocation) -------------
__device__ float g_U[Bn*Nn*Dn];      // U'[b][n][c] = x@W1_top + b1
__device__ float g_V[Bn*Nn*Dn];      // V [b][n][c] = x@W1_bot
__device__ float g_sumU[Nn], g_sumU2[Nn], g_sumV[Nn], g_sumV2[Nn];
__device__ float g_C[Nn*Nn];         // C[s][t] = sum_{b,c} U'[b,s,c]*V[b,t,c]
__device__ float g_f[Bn*Nn*HFn];     // pre-LN features of final MLP
__device__ float g_lnp[2*HFn];       // [0:16) scale, [16:32) shift

__device__ __forceinline__ float leaky(float x) { return x > 0.f ? x : 0.01f * x; }

// ---------------- Kernel A: per-node projections + per-node stats ------------
// grid = N, block = 64 (one thread per batch element)
__global__ void kA(const float* __restrict__ inp, const float* __restrict__ W1,
                   const float* __restrict__ b1) {
    const int n = blockIdx.x;
    const int b = threadIdx.x;     // 0..63
    __shared__ float W1s[64*32];
    __shared__ float red[64*4];
    for (int idx = b; idx < 64*32; idx += 64) W1s[idx] = W1[idx];
    __syncthreads();

    float x[32];
    const float4* xp = (const float4*)(inp + ((size_t)b*Nn + n)*Dn);
    #pragma unroll
    for (int q = 0; q < 8; q++) {
        float4 v = xp[q];
        x[4*q+0]=v.x; x[4*q+1]=v.y; x[4*q+2]=v.z; x[4*q+3]=v.w;
    }
    float su=0.f, su2=0.f, sv=0.f, sv2=0.f;
    float* Uo = g_U + ((size_t)b*Nn + n)*Dn;
    float* Vo = g_V + ((size_t)b*Nn + n)*Dn;
    #pragma unroll 4
    for (int c = 0; c < 32; c++) {
        float u = b1[c];
        float v = 0.f;
        #pragma unroll
        for (int k = 0; k < 32; k++) {
            u += x[k] * W1s[k*32 + c];
            v += x[k] * W1s[(32+k)*32 + c];
        }
        Uo[c] = u; Vo[c] = v;
        su += u; su2 += u*u; sv += v; sv2 += v*v;
    }
    red[b] = su; red[64+b] = su2; red[128+b] = sv; red[192+b] = sv2;
    __syncthreads();
    for (int s = 32; s > 0; s >>= 1) {
        if (b < s) {
            red[b]     += red[b+s];
            red[64+b]  += red[64+b+s];
            red[128+b] += red[128+b+s];
            red[192+b] += red[192+b+s];
        }
        __syncthreads();
    }
    if (b == 0) {
        g_sumU[n]  = red[0];
        g_sumU2[n] = red[64];
        g_sumV[n]  = red[128];
        g_sumV2[n] = red[192];
    }
}

// ---------------- Kernel B: cross term C[s,t], 128x128, K = 64*32 ------------
// grid = (8,8), block = 256 (16x16 tile)
__global__ void kB() {
    const int t0 = blockIdx.x * 16;
    const int s0 = blockIdx.y * 16;
    const int tx = threadIdx.x & 15;
    const int ty = threadIdx.x >> 4;
    __shared__ float Us[16][33];
    __shared__ float Vs[16][33];
    float acc = 0.f;
    for (int b = 0; b < Bn; b++) {
        __syncthreads();
        {
            int idx = threadIdx.x;           // 0..255 -> 2 loads each (512 elems)
            int r = idx >> 5, c = idx & 31;
            Us[r][c] = g_U[((size_t)b*Nn + s0 + r)*Dn + c];
            Vs[r][c] = g_V[((size_t)b*Nn + t0 + r)*Dn + c];
            idx += 256; r = idx >> 5; c = idx & 31;
            Us[r][c] = g_U[((size_t)b*Nn + s0 + r)*Dn + c];
            Vs[r][c] = g_V[((size_t)b*Nn + t0 + r)*Dn + c];
        }
        __syncthreads();
        #pragma unroll
        for (int c = 0; c < 32; c++) acc += Us[ty][c] * Vs[tx][c];
    }
    g_C[(s0+ty)*Nn + (t0+tx)] = acc;
}

// ---------------- Kernel C: fused per-edge MLP (2 batches/block) -------------
// grid = (N, B/2), block = 128. Thread e handles edge p = i*127+e for b0 and b1.
__global__ void __launch_bounds__(128) kC(
        const float* __restrict__ inp,
        const float* __restrict__ W2, const float* __restrict__ b2,
        const float* __restrict__ W3, const float* __restrict__ b3,
        const float* __restrict__ Wf1, const float* __restrict__ bf1,
        const float* __restrict__ g1, const float* __restrict__ be1,
        float* __restrict__ outEdges) {
    const int i  = blockIdx.x;
    const int b0 = blockIdx.y * 2;
    const int b1b = b0 + 1;
    const int e  = threadIdx.x;

    __shared__ float W2t[32*32];    // W2t[c*32+k] = W2[k*32+c]
    __shared__ float W3t[33*32];    // W3t[c*32+k] = W3[k*33+c]
    __shared__ float b2s[32], b3s[33];
    __shared__ float us0[32], us1[32], xs0[32], xs1[32];
    __shared__ float red0[Gn*33], red1[Gn*33];
    __shared__ float red2a[4*32], red2b[4*32];

    for (int idx = e; idx < 1024; idx += 128) {
        int c = idx >> 5, k = idx & 31;
        W2t[idx] = W2[k*32 + c];
    }
    for (int idx = e; idx < 1056; idx += 128) {
        int c = idx >> 5, k = idx & 31;
        W3t[idx] = W3[k*33 + c];
    }
    if (e < 32) {
        b2s[e] = b2[e];
        us0[e] = g_U[((size_t)b0*Nn + i)*Dn + e];
        us1[e] = g_U[((size_t)b1b*Nn + i)*Dn + e];
        xs0[e] = inp[((size_t)b0*Nn + i)*Dn + e];
        xs1[e] = inp[((size_t)b1b*Nn + i)*Dn + e];
    }
    if (e < 33) b3s[e] = b3[e];
    __syncthreads();

    if (e < Gn) {
        const int t = e + (e >= i);
        const int p = i * Gn + e;

        // LN scale/shift inline (depends on p only, shared by both batches)
        const float inv = 1.0f / 2048.0f;
        float m  = (g_sumU[i] + g_sumV[t]) * inv;
        float e2 = (g_sumU2[i] + g_sumV2[t] + 2.0f * g_C[i*Nn + t]) * inv;
        float sc = rsqrtf(e2 - m*m + EPSf) * g1[p];
        float sh = be1[p] - m * sc;

        const float4* vr0 = (const float4*)(g_V + ((size_t)b0*Nn + t)*Dn);
        const float4* vr1 = (const float4*)(g_V + ((size_t)b1b*Nn + t)*Dn);

        float a0[32], a1[32];
        #pragma unroll
        for (int q = 0; q < 8; q++) {
            float4 v0 = vr0[q];
            float4 v1 = vr1[q];
            a0[4*q+0] = leaky((us0[4*q+0] + v0.x) * sc + sh);
            a0[4*q+1] = leaky((us0[4*q+1] + v0.y) * sc + sh);
            a0[4*q+2] = leaky((us0[4*q+2] + v0.z) * sc + sh);
            a0[4*q+3] = leaky((us0[4*q+3] + v0.w) * sc + sh);
            a1[4*q+0] = leaky((us1[4*q+0] + v1.x) * sc + sh);
            a1[4*q+1] = leaky((us1[4*q+1] + v1.y) * sc + sh);
            a1[4*q+2] = leaky((us1[4*q+2] + v1.z) * sc + sh);
            a1[4*q+3] = leaky((us1[4*q+3] + v1.w) * sc + sh);
        }

        // Layer 2: one weight load serves both batches
        float a20[32], a21[32];
        #pragma unroll 2
        for (int c = 0; c < 32; c++) {
            float acc0 = b2s[c], acc1 = b2s[c];
            const float4* wr = (const float4*)(W2t + c*32);
            #pragma unroll
            for (int j = 0; j < 8; j++) {
                float4 w = wr[j];
                acc0 += a0[4*j+0]*w.x; acc1 += a1[4*j+0]*w.x;
                acc0 += a0[4*j+1]*w.y; acc1 += a1[4*j+1]*w.y;
                acc0 += a0[4*j+2]*w.z; acc1 += a1[4*j+2]*w.z;
                acc0 += a0[4*j+3]*w.w; acc1 += a1[4*j+3]*w.w;
            }
            a20[c] = leaky(acc0); a21[c] = leaky(acc1);
        }

        // Layer 3 channel 0 -> edge gates
        float g0 = b3s[0], g1v = b3s[0];
        {
            const float4* wr = (const float4*)(W3t);
            #pragma unroll
            for (int j = 0; j < 8; j++) {
                float4 w = wr[j];
                g0  += a20[4*j+0]*w.x; g1v += a21[4*j+0]*w.x;
                g0  += a20[4*j+1]*w.y; g1v += a21[4*j+1]*w.y;
                g0  += a20[4*j+2]*w.z; g1v += a21[4*j+2]*w.z;
                g0  += a20[4*j+3]*w.w; g1v += a21[4*j+3]*w.w;
            }
        }
        float edge0 = 1.0f / (1.0f + __expf(-g0));
        float edge1 = 1.0f / (1.0f + __expf(-g1v));
        outEdges[(size_t)b0 * Pn + p]  = edge0;
        outEdges[(size_t)b1b * Pn + p] = edge1;

        // Layer 3 channels 1..32 -> weighted messages
        #pragma unroll 2
        for (int c = 1; c < 33; c++) {
            float acc0 = b3s[c], acc1 = b3s[c];
            const float4* wr = (const float4*)(W3t + c*32);
            #pragma unroll
            for (int j = 0; j < 8; j++) {
                float4 w = wr[j];
                acc0 += a20[4*j+0]*w.x; acc1 += a21[4*j+0]*w.x;
                acc0 += a20[4*j+1]*w.y; acc1 += a21[4*j+1]*w.y;
                acc0 += a20[4*j+2]*w.z; acc1 += a21[4*j+2]*w.z;
                acc0 += a20[4*j+3]*w.w; acc1 += a21[4*j+3]*w.w;
            }
            red0[e*33 + (c-1)] = edge0 * acc0;
            red1[e*33 + (c-1)] = edge1 * acc1;
        }
    }
    __syncthreads();

    // stage 1: quarter q sums rows [q*32, min(q*32+32,127)) for channel c
    {
        const int q = e >> 5;
        const int c = e & 31;
        const int r0 = q * 32;
        const int r1 = (q == 3) ? Gn : r0 + 32;
        float s0 = 0.f, s1 = 0.f;
        for (int r = r0; r < r1; r++) {
            s0 += red0[r*33 + c];
            s1 += red1[r*33 + c];
        }
        red2a[q*32 + c] = s0;
        red2b[q*32 + c] = s1;
    }
    __syncthreads();

    if (e < HFn) {
        float acc = bf1[e];
        #pragma unroll
        for (int k = 0; k < 32; k++) acc += xs0[k] * Wf1[k*HFn + e];
        #pragma unroll
        for (int k = 0; k < 32; k++) {
            float aggk = red2a[k] + red2a[32+k] + red2a[64+k] + red2a[96+k];
            acc += aggk * Wf1[(32+k)*HFn + e];
        }
        g_f[((size_t)b0*Nn + i)*HFn + e] = acc;
    } else if (e >= 64 && e < 64 + HFn) {
        const int c = e - 64;
        float acc = bf1[c];
        #pragma unroll
        for (int k = 0; k < 32; k++) acc += xs1[k] * Wf1[k*HFn + c];
        #pragma unroll
        for (int k = 0; k < 32; k++) {
            float aggk = red2b[k] + red2b[32+k] + red2b[64+k] + red2b[96+k];
            acc += aggk * Wf1[(32+k)*HFn + c];
        }
        g_f[((size_t)b1b*Nn + i)*HFn + c] = acc;
    }
}

// ---------------- Kernel E: column stats of f -> LN params -------------------
__global__ void kE(const float* __restrict__ gf, const float* __restrict__ bef) {
    const int tid = threadIdx.x;
    __shared__ float rs[512], rs2[512];
    const int j = tid & 15;
    float s = 0.f, s2 = 0.f;
    #pragma unroll 8
    for (int r = (tid >> 4); r < Bn*Nn; r += 32) {
        float v = g_f[r*HFn + j];
        s += v; s2 += v * v;
    }
    rs[tid] = s; rs2[tid] = s2;
    __syncthreads();
    for (int st = 256; st >= 16; st >>= 1) {
        if (tid < st) { rs[tid] += rs[tid+st]; rs2[tid] += rs2[tid+st]; }
        __syncthreads();
    }
    if (tid < HFn) {
        const float invR = 1.0f / (float)(Bn*Nn);
        float mean = rs[tid] * invR;
        float var  = rs2[tid] * invR - mean * mean;
        float r = rsqrtf(var + EPSf);
        float sc = r * gf[tid];
        g_lnp[tid]       = sc;
        g_lnp[16 + tid]  = bef[tid] - mean * sc;
    }
}

// ---------------- Kernel F: final MLP -> out ---------------------------------
__global__ void kF(const float* __restrict__ Wf2, const float* __restrict__ bf2,
                   float* __restrict__ outp) {
    __shared__ float Wf2s[16*32];
    __shared__ float lnsc[16], lnsh[16], bf2s[32];
    const int tid = threadIdx.x;
    for (int idx = tid; idx < 16*32; idx += 256) Wf2s[idx] = Wf2[idx];
    if (tid < 16) { lnsc[tid] = g_lnp[tid]; lnsh[tid] = g_lnp[16+tid]; }
    if (tid < 32) bf2s[tid] = bf2[tid];
    __syncthreads();

    const int r = blockIdx.x * 256 + tid;   // 0..8191
    float gq[16];
    #pragma unroll
    for (int j = 0; j < 16; j++) {
        float v = g_f[r*HFn + j];
        gq[j] = leaky(v * lnsc[j] + lnsh[j]);
    }
    float4* op = (float4*)(outp + (size_t)r * Dn);
    #pragma unroll
    for (int q = 0; q < 8; q++) {
        float o[4];
        #pragma unroll
        for (int u = 0; u < 4; u++) {
            int c = 4*q + u;
            float acc = bf2s[c];
            #pragma unroll
            for (int j = 0; j < 16; j++) acc += gq[j] * Wf2s[j*32 + c];
            o[u] = acc;
        }
        op[q] = make_float4(o[0], o[1], o[2], o[3]);
    }
}

// ---------------- launch ------------------------------------------------------
extern "C" void kernel_launch(void* const* d_in, const int* in_sizes, int n_in,
                              void* d_out, int out_size) {
    const float* inp = (const float*)d_in[0];
    const float* W1  = (const float*)d_in[3];
    const float* b1  = (const float*)d_in[4];
    const float* g1  = (const float*)d_in[5];
    const float* be1 = (const float*)d_in[6];
    const float* W2  = (const float*)d_in[7];
    const float* b2  = (const float*)d_in[8];
    const float* W3  = (const float*)d_in[9];
    const float* b3  = (const float*)d_in[10];
    const float* Wf1 = (const float*)d_in[11];
    const float* bf1 = (const float*)d_in[12];
    const float* gf  = (const float*)d_in[13];
    const float* bef = (const float*)d_in[14];
    const float* Wf2 = (const float*)d_in[15];
    const float* bf2 = (const float*)d_in[16];

    float* outEdges = (float*)d_out;                       // (B, P)
    float* outFeat  = (float*)d_out + (size_t)Bn * Pn;     // (B, N, D)

    kA<<<Nn, 64>>>(inp, W1, b1);
    kB<<<dim3(8, 8), 256>>>();
    kC<<<dim3(Nn, Bn/2), 128>>>(inp, W2, b2, W3, b3, Wf1, bf1, g1, be1, outEdges);
    kE<<<1, 512>>>(gf, bef);
    kF<<<32, 256>>>(Wf2, bf2, outFeat);
}